// round 12
// baseline (speedup 1.0000x reference)
#include <cuda_runtime.h>
#include <cstdint>

// x [2048, 17, 64, 32] fp32 ->
//  heatmap      [2048,3,16,8]  softmax over 128 of group-summed resized maps
//  max_response [2048,3]       group mean of per-channel maxes of resized maps
//  max_index    [2048,17,2]    (idx%8, idx/8) of per-channel argmax
// resize = jax.image.resize 'linear' (antialias) 1/4: separable 8-tap triangle
// {1,3,5,7,7,5,3,1}/32, border outputs renormalized x(32/28).
//
// R12 = R9's exact pipeline (warp per (n,group), cp.async.cg 5-slot ring,
// 4 chunks (8KB) in flight per warp, refill-before-process, longest-first
// task order) repacked into 3-warp CTAs: 37.1KB smem -> 6 CTAs/SM ->
// 18 warps/SM and 144KB in flight per SM (vs 16 warps / 128KB in R9).

#define VB_STRIDE 37          // 32 + 2 pad each side + 1
#define WARPS_PER_CTA 3
#define CHUNK_FLOATS 512      // 16 rows x 32 cols
#define NSLOTS 5
#define NTASKS 6144

__device__ __forceinline__ void cp_async16(uint32_t dst, const float* src) {
    asm volatile("cp.async.cg.shared.global [%0], [%1], 16;\n"
                 :: "r"(dst), "l"(src));
}
#define CP_COMMIT() asm volatile("cp.async.commit_group;\n" ::: "memory")
#define CP_WAIT3()  asm volatile("cp.async.wait_group 3;\n" ::: "memory")

__global__ __launch_bounds__(32 * WARPS_PER_CTA, 6)
void heatmap_kernel(const float* __restrict__ x, float* __restrict__ out)
{
    __shared__ float ringAll[WARPS_PER_CTA][NSLOTS][CHUNK_FLOATS];  // 30 KB
    __shared__ float hbufAll[WARPS_PER_CTA][16 * VB_STRIDE];        // 6.9 KB

    const int lane = threadIdx.x & 31;
    const int wrp  = threadIdx.x >> 5;
    const int t    = blockIdx.x * WARPS_PER_CTA + wrp;   // 0..6143

    const int g    = 2 - (t >> 11);              // long tasks (g2,g1) first
    const int n    = t & 2047;

    const int ch_beg = (g == 0) ? 0 : (g == 1 ? 5 : 11);
    const int nch    = (g == 0) ? 5 : 6;
    const int Q      = nch * 4;                  // chunks in task

    const float W0 = 1.f / 32.f, W1 = 3.f / 32.f, W2 = 5.f / 32.f, W3 = 7.f / 32.f;
    const float Wt[8] = { W0, W1, W2, W3, W3, W2, W1, W0 };

    float* ring = &ringAll[wrp][0][0];
    float* wb   = &hbufAll[wrp][0];

    // zero hbuf pad columns once (cols 0,1 and 34,35 of 16 rows)
    {
        int vr0 = lane >> 1;
        int o   = (lane & 1) ? 34 : 0;
        wb[vr0 * VB_STRIDE + o]     = 0.f;
        wb[vr0 * VB_STRIDE + o + 1] = 0.f;
    }

    // cp.async lane geometry: 4 rows per round, 8 lanes x 16B per row
    const int prow = lane >> 3;          // 0..3
    const int pcol = (lane & 7) * 4;     // float offset in row

    const float* __restrict__ base = x + ((size_t)n * 17 + ch_beg) * 2048;

    uint32_t ring_u32;
    {
        uint32_t a;
        asm("{ .reg .u64 t2; cvta.to.shared.u64 t2, %1; cvt.u32.u64 %0, t2; }"
            : "=r"(a) : "l"(ring));
        ring_u32 = a;
    }

    // prefetch chunk q into slot (one commit ALWAYS, even when q >= Q)
    #define PREFETCH(q, slotv)                                                 \
        do {                                                                   \
            if ((q) < Q) {                                                     \
                const float* s = base + (size_t)(q) * CHUNK_FLOATS;            \
                _Pragma("unroll")                                              \
                for (int rd = 0; rd < 4; ++rd) {                               \
                    int row = rd * 4 + prow;                                   \
                    cp_async16(ring_u32 +                                      \
                               (uint32_t)(((slotv) * CHUNK_FLOATS +            \
                                           row * 32 + pcol) * 4),              \
                               s + row * 32 + pcol);                           \
                }                                                              \
            }                                                                  \
            CP_COMMIT();                                                       \
        } while (0)

    // prologue: 4 chunks pending
    PREFETCH(0, 0); PREFETCH(1, 1); PREFETCH(2, 2); PREFETCH(3, 3);

    const int vr = lane >> 1;
    const float sc_v = ((vr == 0) | (vr == 15)) ? (32.f / 28.f) : 1.f;
    const float sc_j[4] = {
        sc_v * ((4 * (lane & 1) + 0 == 0) ? (32.f / 28.f) : 1.f),
        sc_v,
        sc_v,
        sc_v * ((4 * (lane & 1) + 3 == 7) ? (32.f / 28.f) : 1.f)
    };

    float gacc[4] = { 0.f, 0.f, 0.f, 0.f };
    float summax  = 0.f;

    float vacc[16];
    #pragma unroll
    for (int i = 0; i < 16; ++i) vacc[i] = 0.f;

    int slot = 0;                        // q % 5, carried
    for (int c = ch_beg; c < ch_beg + nch; ++c) {
        const int crel = c - ch_beg;

        #pragma unroll
        for (int sub = 0; sub < 4; ++sub) {
            const int q = crel * 4 + sub;

            CP_WAIT3();                  // chunk q arrived (4 pending -> 3)
            __syncwarp();                // data visible; prior slot reads done

            // refill FIRST: slot (q+4)%5 was retired at step q-1
            int fslot = slot + 4; if (fslot >= NSLOTS) fslot -= NSLOTS;
            PREFETCH(q + 4, fslot);

            const float* sm = &ring[slot * CHUNK_FLOATS];
            #pragma unroll
            for (int r = 0; r < 16; ++r) {
                float v = sm[r * 32 + lane];
                const int gr  = sub * 16 + r;          // compile-time
                const int vra = (gr + 2) >> 2;
                const int ka  = gr - 4 * vra + 2;      // 0..3
                if (vra < 16) vacc[vra]     += Wt[ka]     * v;
                if (vra >= 1) vacc[vra - 1] += Wt[ka + 4] * v;
            }

            ++slot; if (slot == NSLOTS) slot = 0;
        }

        // ---- channel tail: transpose, h-pass, argmax (overlaps in-flight)
        __syncwarp();
        #pragma unroll
        for (int i = 0; i < 16; ++i)
            wb[i * VB_STRIDE + 2 + lane] = vacc[i];
        __syncwarp();

        float mval = -1e30f;
        int   midx = 0;
        #pragma unroll
        for (int j = 0; j < 4; ++j) {
            const int ow = 4 * (lane & 1) + j;
            const float* h = &wb[vr * VB_STRIDE + 4 * ow];
            float acc = h[0] * W0 + h[1] * W1 + h[2] * W2 + h[3] * W3
                      + h[4] * W3 + h[5] * W2 + h[6] * W1 + h[7] * W0;
            const float val = acc * sc_j[j];
            gacc[j] += val;
            if (val > mval) { mval = val; midx = 4 * lane + j; }
        }
        __syncwarp();   // hbuf reads complete before next channel overwrites

        #pragma unroll
        for (int off = 16; off; off >>= 1) {
            float om = __shfl_down_sync(0xffffffffu, mval, off);
            int   oi = __shfl_down_sync(0xffffffffu, midx, off);
            if (om > mval || (om == mval && oi < midx)) { mval = om; midx = oi; }
        }
        if (lane == 0) {
            summax += mval;
            const size_t o = 792576 + ((size_t)n * 17 + c) * 2;
            out[o + 0] = (float)(midx & 7);
            out[o + 1] = (float)(midx >> 3);
        }

        #pragma unroll
        for (int i = 0; i < 16; ++i) vacc[i] = 0.f;
    }
    #undef PREFETCH

    // ---- warp-local softmax over 128 group-sum values (4 per lane)
    float m = fmaxf(fmaxf(gacc[0], gacc[1]), fmaxf(gacc[2], gacc[3]));
    #pragma unroll
    for (int off = 16; off; off >>= 1)
        m = fmaxf(m, __shfl_xor_sync(0xffffffffu, m, off));

    float e0 = __expf(gacc[0] - m);
    float e1 = __expf(gacc[1] - m);
    float e2 = __expf(gacc[2] - m);
    float e3 = __expf(gacc[3] - m);
    float s  = (e0 + e1) + (e2 + e3);
    #pragma unroll
    for (int off = 16; off; off >>= 1)
        s += __shfl_xor_sync(0xffffffffu, s, off);

    const float inv = 1.f / s;
    float4 o4;
    o4.x = e0 * inv; o4.y = e1 * inv; o4.z = e2 * inv; o4.w = e3 * inv;
    *(float4*)(out + (size_t)n * 384 + (size_t)g * 128 + 4 * lane) = o4;

    if (lane == 0) {
        const float cnt = (g == 0) ? (1.f / 5.f) : (1.f / 6.f);
        out[786432 + (size_t)n * 3 + g] = summax * cnt;
    }
}

extern "C" void kernel_launch(void* const* d_in, const int* in_sizes, int n_in,
                              void* d_out, int out_size)
{
    const float* x = (const float*)d_in[0];
    float* out = (float*)d_out;
    (void)in_sizes; (void)n_in; (void)out_size;

    const int grid = NTASKS / WARPS_PER_CTA;     // 2048
    heatmap_kernel<<<grid, 32 * WARPS_PER_CTA>>>(x, out);
}

// round 13
// speedup vs baseline: 1.0421x; 1.0421x over previous
#include <cuda_runtime.h>
#include <cstdint>

// x [2048, 17, 64, 32] fp32 ->
//  heatmap      [2048,3,16,8]  softmax over 128 of group-summed resized maps
//  max_response [2048,3]       group mean of per-channel maxes of resized maps
//  max_index    [2048,17,2]    (idx%8, idx/8) of per-channel argmax
// resize = jax.image.resize 'linear' (antialias) 1/4: separable 8-tap triangle
// {1,3,5,7,7,5,3,1}/32, border outputs renormalized x(32/28).
//
// R13 = R9 (the measured optimum: warp per (n,group), cp.async.cg 5-slot
// ring, 4 chunks (8KB) in flight per warp, refill-before-process, 4-warp
// group-pure CTAs, 16 warps/SM) with ONE change: longest tasks (g2,g1)
// scheduled first so the ragged final wave is built from short g0 tasks.

#define VB_STRIDE 37          // 32 + 2 pad each side + 1
#define WARPS_PER_CTA 4
#define CHUNK_FLOATS 512      // 16 rows x 32 cols
#define NSLOTS 5

__device__ __forceinline__ void cp_async16(uint32_t dst, const float* src) {
    asm volatile("cp.async.cg.shared.global [%0], [%1], 16;\n"
                 :: "r"(dst), "l"(src));
}
#define CP_COMMIT() asm volatile("cp.async.commit_group;\n" ::: "memory")
#define CP_WAIT3()  asm volatile("cp.async.wait_group 3;\n" ::: "memory")

__global__ __launch_bounds__(32 * WARPS_PER_CTA, 4)
void heatmap_kernel(const float* __restrict__ x, float* __restrict__ out)
{
    __shared__ float ring[WARPS_PER_CTA][NSLOTS][CHUNK_FLOATS];  // 40 KB
    __shared__ float hbuf[WARPS_PER_CTA][16 * VB_STRIDE];        // 9.25 KB

    const int lane = threadIdx.x & 31;
    const int wrp  = threadIdx.x >> 5;
    const int t    = blockIdx.x * WARPS_PER_CTA + wrp;      // 0..6143
    const int g    = 2 - (t >> 11);                         // longest first
    const int n    = t & 2047;

    const int ch_beg = (g == 0) ? 0 : (g == 1 ? 5 : 11);
    const int nch    = (g == 0) ? 5 : 6;
    const int Q      = nch * 4;                              // chunks in task

    const float W0 = 1.f / 32.f, W1 = 3.f / 32.f, W2 = 5.f / 32.f, W3 = 7.f / 32.f;
    const float Wt[8] = { W0, W1, W2, W3, W3, W2, W1, W0 };

    float* wb = hbuf[wrp];

    // zero hbuf pad columns once (cols 0,1 and 34,35 of 16 rows)
    {
        int vr0 = lane >> 1;
        int o   = (lane & 1) ? 34 : 0;
        wb[vr0 * VB_STRIDE + o]     = 0.f;
        wb[vr0 * VB_STRIDE + o + 1] = 0.f;
    }

    // cp.async lane geometry: 4 rows per round, 8 lanes x 16B per row
    const int prow = lane >> 3;          // 0..3
    const int pcol = (lane & 7) * 4;     // float offset in row

    const float* __restrict__ base = x + ((size_t)n * 17 + ch_beg) * 2048;

    uint32_t ring_u32;
    {
        uint32_t a;
        asm("{ .reg .u64 t2; cvta.to.shared.u64 t2, %1; cvt.u32.u64 %0, t2; }"
            : "=r"(a) : "l"(&ring[wrp][0][0]));
        ring_u32 = a;
    }

    // prefetch chunk q into slot (one commit ALWAYS, even when q >= Q)
    #define PREFETCH(q, slotv)                                                 \
        do {                                                                   \
            if ((q) < Q) {                                                     \
                const float* s = base + (size_t)(q) * CHUNK_FLOATS;            \
                _Pragma("unroll")                                              \
                for (int rd = 0; rd < 4; ++rd) {                               \
                    int row = rd * 4 + prow;                                   \
                    cp_async16(ring_u32 +                                      \
                               (uint32_t)(((slotv) * CHUNK_FLOATS +            \
                                           row * 32 + pcol) * 4),              \
                               s + row * 32 + pcol);                           \
                }                                                              \
            }                                                                  \
            CP_COMMIT();                                                       \
        } while (0)

    // prologue: 4 chunks pending
    PREFETCH(0, 0); PREFETCH(1, 1); PREFETCH(2, 2); PREFETCH(3, 3);

    const int vr = lane >> 1;
    const float sc_v = ((vr == 0) | (vr == 15)) ? (32.f / 28.f) : 1.f;
    const float sc_j[4] = {
        sc_v * ((4 * (lane & 1) + 0 == 0) ? (32.f / 28.f) : 1.f),
        sc_v,
        sc_v,
        sc_v * ((4 * (lane & 1) + 3 == 7) ? (32.f / 28.f) : 1.f)
    };

    float gacc[4] = { 0.f, 0.f, 0.f, 0.f };
    float summax  = 0.f;

    float vacc[16];
    #pragma unroll
    for (int i = 0; i < 16; ++i) vacc[i] = 0.f;

    int slot = 0;                        // q % 5, carried
    for (int c = ch_beg; c < ch_beg + nch; ++c) {
        const int crel = c - ch_beg;

        #pragma unroll
        for (int sub = 0; sub < 4; ++sub) {
            const int q = crel * 4 + sub;

            CP_WAIT3();                  // chunk q arrived (4 pending -> 3)
            __syncwarp();                // data visible; prior slot reads done

            // refill FIRST: slot (q+4)%5 was retired at step q-1
            int fslot = slot + 4; if (fslot >= NSLOTS) fslot -= NSLOTS;
            PREFETCH(q + 4, fslot);

            const float* sm = &ring[wrp][slot][0];
            #pragma unroll
            for (int r = 0; r < 16; ++r) {
                float v = sm[r * 32 + lane];
                const int gr  = sub * 16 + r;          // compile-time
                const int vra = (gr + 2) >> 2;
                const int ka  = gr - 4 * vra + 2;      // 0..3
                if (vra < 16) vacc[vra]     += Wt[ka]     * v;
                if (vra >= 1) vacc[vra - 1] += Wt[ka + 4] * v;
            }

            ++slot; if (slot == NSLOTS) slot = 0;
        }

        // ---- channel tail: transpose, h-pass, argmax (overlaps in-flight)
        __syncwarp();
        #pragma unroll
        for (int i = 0; i < 16; ++i)
            wb[i * VB_STRIDE + 2 + lane] = vacc[i];
        __syncwarp();

        float mval = -1e30f;
        int   midx = 0;
        #pragma unroll
        for (int j = 0; j < 4; ++j) {
            const int ow = 4 * (lane & 1) + j;
            const float* h = &wb[vr * VB_STRIDE + 4 * ow];
            float acc = h[0] * W0 + h[1] * W1 + h[2] * W2 + h[3] * W3
                      + h[4] * W3 + h[5] * W2 + h[6] * W1 + h[7] * W0;
            const float val = acc * sc_j[j];
            gacc[j] += val;
            if (val > mval) { mval = val; midx = 4 * lane + j; }
        }
        __syncwarp();   // hbuf reads complete before next channel overwrites

        #pragma unroll
        for (int off = 16; off; off >>= 1) {
            float om = __shfl_down_sync(0xffffffffu, mval, off);
            int   oi = __shfl_down_sync(0xffffffffu, midx, off);
            if (om > mval || (om == mval && oi < midx)) { mval = om; midx = oi; }
        }
        if (lane == 0) {
            summax += mval;
            const size_t o = 792576 + ((size_t)n * 17 + c) * 2;
            out[o + 0] = (float)(midx & 7);
            out[o + 1] = (float)(midx >> 3);
        }

        #pragma unroll
        for (int i = 0; i < 16; ++i) vacc[i] = 0.f;
    }
    #undef PREFETCH

    // ---- warp-local softmax over 128 group-sum values (4 per lane)
    float m = fmaxf(fmaxf(gacc[0], gacc[1]), fmaxf(gacc[2], gacc[3]));
    #pragma unroll
    for (int off = 16; off; off >>= 1)
        m = fmaxf(m, __shfl_xor_sync(0xffffffffu, m, off));

    float e0 = __expf(gacc[0] - m);
    float e1 = __expf(gacc[1] - m);
    float e2 = __expf(gacc[2] - m);
    float e3 = __expf(gacc[3] - m);
    float s  = (e0 + e1) + (e2 + e3);
    #pragma unroll
    for (int off = 16; off; off >>= 1)
        s += __shfl_xor_sync(0xffffffffu, s, off);

    const float inv = 1.f / s;
    float4 o4;
    o4.x = e0 * inv; o4.y = e1 * inv; o4.z = e2 * inv; o4.w = e3 * inv;
    *(float4*)(out + (size_t)n * 384 + (size_t)g * 128 + 4 * lane) = o4;

    if (lane == 0) {
        const float cnt = (g == 0) ? (1.f / 5.f) : (1.f / 6.f);
        out[786432 + (size_t)n * 3 + g] = summax * cnt;
    }
}

extern "C" void kernel_launch(void* const* d_in, const int* in_sizes, int n_in,
                              void* d_out, int out_size)
{
    const float* x = (const float*)d_in[0];
    float* out = (float*)d_out;
    (void)in_sizes; (void)n_in; (void)out_size;
    heatmap_kernel<<<2048 * 3 / WARPS_PER_CTA, 32 * WARPS_PER_CTA>>>(x, out);
}

// round 14
// speedup vs baseline: 1.0491x; 1.0067x over previous
#include <cuda_runtime.h>
#include <cstdint>

// x [2048, 17, 64, 32] fp32 ->
//  heatmap      [2048,3,16,8]  softmax over 128 of group-summed resized maps
//  max_response [2048,3]       group mean of per-channel maxes of resized maps
//  max_index    [2048,17,2]    (idx%8, idx/8) of per-channel argmax
// resize = jax.image.resize 'linear' (antialias) 1/4: separable 8-tap triangle
// {1,3,5,7,7,5,3,1}/32, border outputs renormalized x(32/28).
//
// R14 = R9's per-warp pipeline (cp.async.cg 5-slot ring, 4 chunks (8KB) in
// flight, refill-before-process) in 2-WARP CTAs with smem padded to 28.4KB
// so exactly 8 CTAs (16 warps) are resident per SM -- the measured optimal
// warp count, at 2x finer CTA granularity than R9 (3072 CTAs).

#define VB_STRIDE 37          // 32 + 2 pad each side + 1
#define WARPS_PER_CTA 2
#define CHUNK_FLOATS 512      // 16 rows x 32 cols
#define NSLOTS 5
#define PAD_FLOATS 944        // pad CTA smem to ~28.4KB -> 8 CTAs/SM

__device__ __forceinline__ void cp_async16(uint32_t dst, const float* src) {
    asm volatile("cp.async.cg.shared.global [%0], [%1], 16;\n"
                 :: "r"(dst), "l"(src));
}
#define CP_COMMIT() asm volatile("cp.async.commit_group;\n" ::: "memory")
#define CP_WAIT3()  asm volatile("cp.async.wait_group 3;\n" ::: "memory")

__global__ __launch_bounds__(32 * WARPS_PER_CTA, 8)
void heatmap_kernel(const float* __restrict__ x, float* __restrict__ out)
{
    __shared__ float ring[WARPS_PER_CTA][NSLOTS][CHUNK_FLOATS];  // 20 KB
    __shared__ float hbuf[WARPS_PER_CTA][16 * VB_STRIDE];        // 4.6 KB
    __shared__ float padsm[PAD_FLOATS];                          // 3.7 KB pad

    const int lane = threadIdx.x & 31;
    const int wrp  = threadIdx.x >> 5;
    const int t    = blockIdx.x * WARPS_PER_CTA + wrp;      // 0..6143
    const int g    = 2 - (t >> 11);                         // longest first
    const int n    = t & 2047;

    // keep the pad array alive without touching memory meaningfully
    if (threadIdx.x == 0xFFFF) padsm[0] = 0.f;

    const int ch_beg = (g == 0) ? 0 : (g == 1 ? 5 : 11);
    const int nch    = (g == 0) ? 5 : 6;
    const int Q      = nch * 4;                              // chunks in task

    const float W0 = 1.f / 32.f, W1 = 3.f / 32.f, W2 = 5.f / 32.f, W3 = 7.f / 32.f;
    const float Wt[8] = { W0, W1, W2, W3, W3, W2, W1, W0 };

    float* wb = hbuf[wrp];

    // zero hbuf pad columns once (cols 0,1 and 34,35 of 16 rows)
    {
        int vr0 = lane >> 1;
        int o   = (lane & 1) ? 34 : 0;
        wb[vr0 * VB_STRIDE + o]     = 0.f;
        wb[vr0 * VB_STRIDE + o + 1] = 0.f;
    }

    // cp.async lane geometry: 4 rows per round, 8 lanes x 16B per row
    const int prow = lane >> 3;          // 0..3
    const int pcol = (lane & 7) * 4;     // float offset in row

    const float* __restrict__ base = x + ((size_t)n * 17 + ch_beg) * 2048;

    uint32_t ring_u32;
    {
        uint32_t a;
        asm("{ .reg .u64 t2; cvta.to.shared.u64 t2, %1; cvt.u32.u64 %0, t2; }"
            : "=r"(a) : "l"(&ring[wrp][0][0]));
        ring_u32 = a;
    }

    // prefetch chunk q into slot (one commit ALWAYS, even when q >= Q)
    #define PREFETCH(q, slotv)                                                 \
        do {                                                                   \
            if ((q) < Q) {                                                     \
                const float* s = base + (size_t)(q) * CHUNK_FLOATS;            \
                _Pragma("unroll")                                              \
                for (int rd = 0; rd < 4; ++rd) {                               \
                    int row = rd * 4 + prow;                                   \
                    cp_async16(ring_u32 +                                      \
                               (uint32_t)(((slotv) * CHUNK_FLOATS +            \
                                           row * 32 + pcol) * 4),              \
                               s + row * 32 + pcol);                           \
                }                                                              \
            }                                                                  \
            CP_COMMIT();                                                       \
        } while (0)

    // prologue: 4 chunks pending
    PREFETCH(0, 0); PREFETCH(1, 1); PREFETCH(2, 2); PREFETCH(3, 3);

    const int vr = lane >> 1;
    const float sc_v = ((vr == 0) | (vr == 15)) ? (32.f / 28.f) : 1.f;
    const float sc_j[4] = {
        sc_v * ((4 * (lane & 1) + 0 == 0) ? (32.f / 28.f) : 1.f),
        sc_v,
        sc_v,
        sc_v * ((4 * (lane & 1) + 3 == 7) ? (32.f / 28.f) : 1.f)
    };

    float gacc[4] = { 0.f, 0.f, 0.f, 0.f };
    float summax  = 0.f;

    float vacc[16];
    #pragma unroll
    for (int i = 0; i < 16; ++i) vacc[i] = 0.f;

    int slot = 0;                        // q % 5, carried
    for (int c = ch_beg; c < ch_beg + nch; ++c) {
        const int crel = c - ch_beg;

        #pragma unroll
        for (int sub = 0; sub < 4; ++sub) {
            const int q = crel * 4 + sub;

            CP_WAIT3();                  // chunk q arrived (4 pending -> 3)
            __syncwarp();                // data visible; prior slot reads done

            // refill FIRST: slot (q+4)%5 was retired at step q-1
            int fslot = slot + 4; if (fslot >= NSLOTS) fslot -= NSLOTS;
            PREFETCH(q + 4, fslot);

            const float* sm = &ring[wrp][slot][0];
            #pragma unroll
            for (int r = 0; r < 16; ++r) {
                float v = sm[r * 32 + lane];
                const int gr  = sub * 16 + r;          // compile-time
                const int vra = (gr + 2) >> 2;
                const int ka  = gr - 4 * vra + 2;      // 0..3
                if (vra < 16) vacc[vra]     += Wt[ka]     * v;
                if (vra >= 1) vacc[vra - 1] += Wt[ka + 4] * v;
            }

            ++slot; if (slot == NSLOTS) slot = 0;
        }

        // ---- channel tail: transpose, h-pass, argmax (overlaps in-flight)
        __syncwarp();
        #pragma unroll
        for (int i = 0; i < 16; ++i)
            wb[i * VB_STRIDE + 2 + lane] = vacc[i];
        __syncwarp();

        float mval = -1e30f;
        int   midx = 0;
        #pragma unroll
        for (int j = 0; j < 4; ++j) {
            const int ow = 4 * (lane & 1) + j;
            const float* h = &wb[vr * VB_STRIDE + 4 * ow];
            float acc = h[0] * W0 + h[1] * W1 + h[2] * W2 + h[3] * W3
                      + h[4] * W3 + h[5] * W2 + h[6] * W1 + h[7] * W0;
            const float val = acc * sc_j[j];
            gacc[j] += val;
            if (val > mval) { mval = val; midx = 4 * lane + j; }
        }
        __syncwarp();   // hbuf reads complete before next channel overwrites

        #pragma unroll
        for (int off = 16; off; off >>= 1) {
            float om = __shfl_down_sync(0xffffffffu, mval, off);
            int   oi = __shfl_down_sync(0xffffffffu, midx, off);
            if (om > mval || (om == mval && oi < midx)) { mval = om; midx = oi; }
        }
        if (lane == 0) {
            summax += mval;
            const size_t o = 792576 + ((size_t)n * 17 + c) * 2;
            out[o + 0] = (float)(midx & 7);
            out[o + 1] = (float)(midx >> 3);
        }

        #pragma unroll
        for (int i = 0; i < 16; ++i) vacc[i] = 0.f;
    }
    #undef PREFETCH

    // ---- warp-local softmax over 128 group-sum values (4 per lane)
    float m = fmaxf(fmaxf(gacc[0], gacc[1]), fmaxf(gacc[2], gacc[3]));
    #pragma unroll
    for (int off = 16; off; off >>= 1)
        m = fmaxf(m, __shfl_xor_sync(0xffffffffu, m, off));

    float e0 = __expf(gacc[0] - m);
    float e1 = __expf(gacc[1] - m);
    float e2 = __expf(gacc[2] - m);
    float e3 = __expf(gacc[3] - m);
    float s  = (e0 + e1) + (e2 + e3);
    #pragma unroll
    for (int off = 16; off; off >>= 1)
        s += __shfl_xor_sync(0xffffffffu, s, off);

    const float inv = 1.f / s;
    float4 o4;
    o4.x = e0 * inv; o4.y = e1 * inv; o4.z = e2 * inv; o4.w = e3 * inv;
    *(float4*)(out + (size_t)n * 384 + (size_t)g * 128 + 4 * lane) = o4;

    if (lane == 0) {
        const float cnt = (g == 0) ? (1.f / 5.f) : (1.f / 6.f);
        out[786432 + (size_t)n * 3 + g] = summax * cnt;
    }
}

extern "C" void kernel_launch(void* const* d_in, const int* in_sizes, int n_in,
                              void* d_out, int out_size)
{
    const float* x = (const float*)d_in[0];
    float* out = (float*)d_out;
    (void)in_sizes; (void)n_in; (void)out_size;
    heatmap_kernel<<<2048 * 3 / WARPS_PER_CTA, 32 * WARPS_PER_CTA>>>(x, out);
}